// round 14
// baseline (speedup 1.0000x reference)
#include <cuda_runtime.h>
#include <cuda_bf16.h>

typedef unsigned long long u64;
typedef unsigned int u32;

#define NB 64
#define NS 100
#define NQ 129
#define DD 128

// -------------------- device scratch ---------------------------------------
__device__ __align__(16) float g_AL [NB*NS*DD];
__device__ __align__(16) float g_G23[NB*NS*2*DD];
__device__ __align__(16) float g_UIT[NB*NS*DD];
__device__ __align__(16) float g_HT [NB*NS*DD];
__device__ __align__(16) float g_W5T [DD*2*DD];   // [f][k]
__device__ __align__(16) float g_w1s [DD];
__device__ __align__(16) float g_QS  [NB*NS];

__device__ __forceinline__ float sigm(float x) {
    return __fdividef(1.f, 1.f + __expf(-x));
}
#define FMA2(d, a, bb) asm("fma.rn.f32x2 %0, %1, %2, %0;" : "+l"(d) : "l"(a), "l"(bb))
__device__ __forceinline__ float2 unpk(u64 v) {
    float2 r;
    asm("mov.b64 {%0, %1}, %2;" : "=f"(r.x), "=f"(r.y) : "l"(v));
    return r;
}
__device__ __forceinline__ u32 smem_u32(const void* p) {
    u32 a;
    asm("{ .reg .u64 t; cvta.to.shared.u64 t, %1; cvt.u32.u64 %0, t; }" : "=r"(a) : "l"(p));
    return a;
}
__device__ __forceinline__ u32 mapa_u32(u32 laddr, u32 r) {
    u32 a;
    asm("mapa.shared::cluster.u32 %0, %1, %2;" : "=r"(a) : "r"(laddr), "r"(r));
    return a;
}
__device__ __forceinline__ void st_cluster_f32(u32 raddr, float v) {
    asm volatile("st.shared::cluster.f32 [%0], %1;" :: "r"(raddr), "f"(v) : "memory");
}
__device__ __forceinline__ void st_async_f32(u32 raddr, float v, u32 rmbar) {
    asm volatile("st.async.shared::cluster.mbarrier::complete_tx::bytes.f32 [%0], %1, [%2];"
                 :: "r"(raddr), "f"(v), "r"(rmbar) : "memory");
}
#define CLUSTER_SYNC() do { \
    asm volatile("barrier.cluster.arrive.aligned;" ::: "memory"); \
    asm volatile("barrier.cluster.wait.aligned;"   ::: "memory"); \
} while (0)
#define MBARRIER_INIT(mb, c) \
    asm volatile("mbarrier.init.shared.b64 [%0], %1;" :: "r"((u32)(mb)), "r"((u32)(c)) : "memory")
#define MBAR_EXPECT_TX(mb, bytes) \
    asm volatile("mbarrier.arrive.expect_tx.shared.b64 _, [%0], %1;" \
                 :: "r"((u32)(mb)), "r"((u32)(bytes)) : "memory")
#define MBAR_WAIT(mb, par) do { \
    u32 _m = (u32)(mb), _p = (u32)(par), _d; \
    asm volatile("{ .reg .pred p; mbarrier.try_wait.parity.acquire.cta.shared::cta.b64 p, [%1], %2; selp.b32 %0, 1, 0, p; }" \
                 : "=r"(_d) : "r"(_m), "r"(_p) : "memory"); \
    if (!_d) { \
        asm volatile("{ .reg .pred P1; WL_%=: mbarrier.try_wait.parity.acquire.cta.shared::cta.b64 P1, [%0], %1, 0x989680; @P1 bra.uni WD_%=; bra.uni WL_%=; WD_%=: }" \
                     :: "r"(_m), "r"(_p) : "memory"); \
    } \
} while (0)
#define BAR_CHAIN()   asm volatile("bar.sync 1, 256;" ::: "memory")
#define BAR3_SYNC()   asm volatile("bar.sync 3, 768;" ::: "memory")
#define BAR3_ARRIVE() asm volatile("bar.arrive 3, 768;" ::: "memory")
#define BAR4_SYNC()   asm volatile("bar.sync 4, 768;" ::: "memory")
#define BAR4_ARRIVE() asm volatile("bar.arrive 4, 768;" ::: "memory")

// ============================ prep kernels (3) ==============================
__global__ void prep_base(const float* __restrict__ W1, const float* __restrict__ W5,
                          const int* __restrict__ e_data, const float* __restrict__ q_matrix)
{
    for (int idx = blockIdx.x*blockDim.x + threadIdx.x; idx < 32896;
         idx += gridDim.x*blockDim.x) {
        if (idx < 32768) {
            int f = idx >> 8, k = idx & 255;
            g_W5T[idx] = W5[k*128 + f];
        } else {
            int f = idx - 32768;
            float s = 0.f;
            for (int k = 0; k < 128; k++) s += W1[(256+k)*128 + f];
            g_w1s[f] = s;
        }
    }
    int lane = threadIdx.x & 31;
    int gw = (blockIdx.x*blockDim.x + threadIdx.x) >> 5;
    int nw = (gridDim.x*blockDim.x) >> 5;
    for (int item = gw; item < NB*NS; item += nw) {
        const float* q = q_matrix + (long)e_data[item]*NQ;
        float s = 0.f;
        for (int i = lane; i < NQ; i += 32) s += q[i];
        s += __shfl_xor_sync(0xffffffffu, s, 16);
        s += __shfl_xor_sync(0xffffffffu, s, 8);
        s += __shfl_xor_sync(0xffffffffu, s, 4);
        s += __shfl_xor_sync(0xffffffffu, s, 2);
        s += __shfl_xor_sync(0xffffffffu, s, 1);
        if (lane == 0) g_QS[item] = s;
    }
}

__global__ void __launch_bounds__(128) prep_ALUIT(
    const int* __restrict__ e_data, const int* __restrict__ a_data,
    const int* __restrict__ at_data, const int* __restrict__ it_data,
    const float* __restrict__ E_e, const float* __restrict__ E_at,
    const float* __restrict__ E_it,
    const float* __restrict__ W1, const float* __restrict__ b1,
    const float* __restrict__ W4, const float* __restrict__ b4)
{
    int b = blockIdx.x, s0 = blockIdx.y*8, f = threadIdx.x;
    __shared__ float se[8][128], sa[8][128], si[8][128], av[8];
    int cnt = min(8, NS - s0);
    for (int t = 0; t < 8; t++) {
        if (t < cnt) {
            int s = s0 + t;
            se[t][f] = E_e [e_data [b*NS + s]*128 + f];
            sa[t][f] = E_at[at_data[b*NS + s]*128 + f];
            si[t][f] = E_it[it_data[b*NS + s]*128 + f];
            if (f == 0) av[t] = (float)a_data[b*NS + s];
        } else { se[t][f] = 0.f; sa[t][f] = 0.f; si[t][f] = 0.f; if (f == 0) av[t] = 0.f; }
    }
    __syncthreads();
    float w1sf = g_w1s[f], b1f = b1[f], b4f = b4[f];
    float acc[8], acu[8];
#pragma unroll
    for (int t = 0; t < 8; t++) { acc[t] = b1f + av[t]*w1sf; acu[t] = b4f; }
    for (int k = 0; k < 128; k++) {
        float w = W1[k*128 + f];
#pragma unroll
        for (int t = 0; t < 8; t++) acc[t] += se[t][k]*w;
    }
    for (int k = 0; k < 128; k++) {
        float w = W1[(128+k)*128 + f];
#pragma unroll
        for (int t = 0; t < 8; t++) acc[t] += sa[t][k]*w;
    }
    for (int k = 0; k < 128; k++) {
        float w = W4[(256+k)*128 + f];
#pragma unroll
        for (int t = 0; t < 8; t++) acu[t] += si[t][k]*w;
    }
    for (int t = 0; t < cnt; t++) {
        g_AL [(b*NS + s0 + t)*128 + f] = acc[t];
        g_UIT[(b*NS + s0 + t)*128 + f] = acu[t];
    }
}

__global__ void __launch_bounds__(256) prep_G23(
    const int* __restrict__ it_data, const float* __restrict__ E_it,
    const float* __restrict__ W2, const float* __restrict__ b2,
    const float* __restrict__ W3, const float* __restrict__ b3)
{
    int b = blockIdx.x, t0 = blockIdx.y*10;
    int T = min(10, 99 - t0);
    __shared__ float sf[10][384];
    for (int idx = threadIdx.x; idx < T*384; idx += 256) {
        int tt = idx / 384, kk = idx - tt*384;
        int t = t0 + tt;
        float v;
        if (kk < 128)       v = (t == 0) ? 0.f : g_AL[(b*NS + t - 1)*128 + kk];
        else if (kk < 256) { int it = it_data[b*NS + t]; v = E_it[it*128 + (kk-128)]; }
        else                v = g_AL[(b*NS + t)*128 + (kk-256)];
        sf[tt][kk] = v;
    }
    __syncthreads();
    int j = threadIdx.x;
    const float* Wc;
    float bias;
    if (j < 128) { Wc = W2 + j;        bias = b2[j];     }
    else         { Wc = W3 + (j-128);  bias = b3[j-128]; }
    float acc[10];
#pragma unroll
    for (int tt = 0; tt < 10; tt++) acc[tt] = bias;
    for (int k = 0; k < 384; k++) {
        float wv = Wc[k*128];
#pragma unroll
        for (int tt = 0; tt < 10; tt++) acc[tt] += sf[tt][k]*wv;
    }
    for (int tt = 0; tt < T; tt++) g_G23[(b*NS + t0 + tt)*256 + j] = acc[tt];
}

// ============================ main scan =====================================
// 2-CTA cluster per b, 768 threads. Warps 0..15: GEMM, organized as
// 8 row-groups x 2 col-halves (each warp: 8 rows x 64 cols). W crossbar
// traffic stays at the 8-warp level while 4 warps/SMSP hide LDS latency.
// Warps 16..23: chain.
#define OFF_SH     0        // 8192
#define OFF_SH128  8192     // 128
#define OFF_W4H    8320     // 16384 (k-pair interleaved)
#define OFF_W4L    24704    // 16384 [k][f]
#define OFF_LG     41088    // 128
#define OFF_C      41216    // 128
#define OFF_HT     41344    // 128
#define OFF_Q      41472    // 264
#define OFF_PART   41736    // 16*64 = 1024 (also 512 scratch for ht0)
#define OFF_CP     43784    // 256
#define OFF_GP     44040    // 256
#define OFF_G2P    44296    // 256
#define OFF_G3P    44552    // 256
#define OFF_PHT    44808    // 128
#define OFF_MBAR   44936    // u64 mbar
#define SMEM_FLOATS 44940   // 179,760 B

__global__ void __launch_bounds__(768, 1) __cluster_dims__(2, 1, 1) lpkt_main(
    const int* __restrict__ e_data, const float* __restrict__ q_matrix,
    const float* __restrict__ h0, const float* __restrict__ W4,
    const float* __restrict__ W2, const float* __restrict__ W3)
{
    extern __shared__ float sm[];
    float* sh    = sm + OFF_SH;
    float* sh128 = sm + OFF_SH128;
    float* sW4h  = sm + OFF_W4H;
    float* sW4l  = sm + OFF_W4L;
    float* sLG   = sm + OFF_LG;
    float* sC    = sm + OFF_C;
    float* sHT   = sm + OFF_HT;
    float* sQ    = sm + OFF_Q;
    float* sPart = sm + OFF_PART;
    float* sCp   = sm + OFF_CP;
    float* sGp   = sm + OFF_GP;
    float* sG2p  = sm + OFF_G2P;
    float* sG3p  = sm + OFF_G3P;
    float* pHT   = sm + OFF_PHT;

    u32 rank;
    asm("mov.u32 %0, %%cluster_ctarank;" : "=r"(rank));
    const u32 peer = rank ^ 1u;
    const int b = blockIdx.x >> 1;
    const int tid = threadIdx.x;
    const int w = tid >> 5, lane = tid & 31;

    const u32 sb   = smem_u32(sm);
    const u32 mbT  = sb + OFF_MBAR*4;
    const u32 rmbT = mapa_u32(mbT, peer);
    const u32 rPHT = mapa_u32(sb + OFF_PHT*4, peer);

    // ---- init ----
    for (int idx = tid; idx < 16384; idx += 768) {
        int k = idx >> 7, c = idx & 127;
        sW4h[(k >> 1)*256 + 2*c + (k & 1)] = W4[idx];   // k-pair interleave
        sW4l[idx] = W4[16384 + idx];
    }
    for (int idx = tid; idx < 8192; idx += 768) sh[idx] = h0[rank*8192 + idx];
    if (tid < 128) sh128[tid] = h0[16384 + tid];
    if (tid < NQ) sQ[tid] = q_matrix[(long)e_data[b*NS]*NQ + tid];
    if (tid == 0) MBARRIER_INIT(mbT, 1);
    __syncthreads();
    CLUSTER_SYNC();

    // ---- ht0 ----
    if (tid < 512) {
        int f = tid & 127, qtr = tid >> 7;
        float acc = 0.f;
        for (int rr = 0; rr < 16; rr++) {
            int rl = qtr*16 + rr;
            acc += sQ[rank*64 + rl]*sh[rl*128 + f];
        }
        sPart[tid] = acc;
    }
    __syncthreads();
    float own0 = 0.f;
    if (tid < 128) {
        own0 = sPart[tid] + sPart[128+tid] + sPart[256+tid] + sPart[384+tid];
        st_cluster_f32(rPHT + tid*4, own0);
    }
    CLUSTER_SYNC();
    if (tid < 128)
        sHT[tid] = __fdividef(own0 + pHT[tid] + sQ[128]*sh128[tid], g_QS[b*NS]);
    __syncthreads();

    const int rbase = (w & 7)*8;     // row group (8 rows)
    const int colh  = w >> 3;        // col half (0/1) among GEMM warps
    const int c0    = colh*64;

    for (int t = 0; t < 99; t++) {
        const float* sQE = sQ + (t & 1)*132;
        float*       sQN = sQ + ((t + 1) & 1)*132;

        if (w < 16) {
            // ====== GEMM warps: 8 rows x 64 cols, cols {c0+2l, c0+2l+1} ======
            u64 acc0[8], acc1[8];
#pragma unroll
            for (int j = 0; j < 8; j++) { acc0[j] = 0ull; acc1[j] = 0ull; }
            const ulonglong2* Wq = (const ulonglong2*)sW4h;  // [m][64] ull2
            const ulonglong2* Hq = (const ulonglong2*)sh;    // [r][32] ull2
            const int wcol = colh*32 + lane;
#pragma unroll 4
            for (int k4 = 0; k4 < 32; k4++) {
                ulonglong2 wa = Wq[(2*k4    )*64 + wcol];    // (k0,k1) x (c,c+1)
                ulonglong2 wb = Wq[(2*k4 + 1)*64 + wcol];    // (k2,k3) x (c,c+1)
#pragma unroll
                for (int j = 0; j < 8; j++) {
                    ulonglong2 hq = Hq[(rbase + j)*32 + k4];
                    FMA2(acc0[j], hq.x, wa.x);
                    FMA2(acc1[j], hq.x, wa.y);
                    FMA2(acc0[j], hq.y, wb.x);
                    FMA2(acc1[j], hq.y, wb.y);
                }
            }
            BAR3_SYNC();                       // wait: sLG/sC/sQN ready

            float2 lg = ((const float2*)(sLG + c0))[lane];
            float2 cc = ((const float2*)(sC  + c0))[lane];
            float htp0 = 0.f, htp1 = 0.f;
#pragma unroll
            for (int j = 0; j < 8; j++) {
                int rl = rbase + j;
                int rg = rank*64 + rl;
                float2 a0 = unpk(acc0[j]);
                float2 a1 = unpk(acc1[j]);
                float g0 = a0.x + a0.y + cc.x;
                float g1 = a1.x + a1.y + cc.y;
                float qe = sQE[rg], qn = sQN[rg];
                float2 hv = ((const float2*)(sh + rl*128 + c0))[lane];
                float2 hn;
                hn.x = qe*lg.x + sigm(g0)*hv.x;
                hn.y = qe*lg.y + sigm(g1)*hv.y;
                ((float2*)(sh + rl*128 + c0))[lane] = hn;
                htp0 += qn*hn.x;
                htp1 += qn*hn.y;
            }
            ((float2*)(sPart + w*64))[lane] = make_float2(htp0, htp1);
            BAR4_ARRIVE();                     // sPart published; roll on
        } else {
            // ================= chain warps =================
            const int ct = tid - 512;
            if (ct == 0) MBAR_EXPECT_TX(mbT, 512);
            float ureg = 0.f;
            if (ct < 128) ureg = g_UIT[(b*NS + t)*128 + ct];
            if (ct < NQ) sQN[ct] = q_matrix[(long)e_data[b*NS + t + 1]*NQ + ct];

            // G partials: k-split halves, both W2 & W3 dots per thread
            {
                int j = ct & 127, kk0 = (ct >> 7)*64;
                const float* W2c = W2 + (384 + kk0)*128 + j;
                const float* W3c = W3 + (384 + kk0)*128 + j;
                const float* hpt = sHT + kk0;
                float a2[4] = {0.f, 0.f, 0.f, 0.f};
                float a3[4] = {0.f, 0.f, 0.f, 0.f};
#pragma unroll 8
                for (int kk = 0; kk < 64; kk++) {
                    float hv = hpt[kk];
                    a2[kk & 3] += hv*W2c[kk*128];
                    a3[kk & 3] += hv*W3c[kk*128];
                }
                sG2p[ct] = (a2[0] + a2[1]) + (a2[2] + a2[3]);
                sG3p[ct] = (a3[0] + a3[1]) + (a3[2] + a3[3]);
            }
            BAR_CHAIN();
            if (ct < 128) {
                const float* gb = g_G23 + (b*NS + t)*256;
                float g2 = sG2p[ct] + sG2p[128 + ct] + gb[ct];
                float g3 = sG3p[ct] + sG3p[128 + ct] + gb[128 + ct];
                sLG[ct] = sigm(g3) * sigm(2.f*g2);
            }
            BAR_CHAIN();

            // c = LG @ W4l ; g128 = h128 @ W4h  (k split in halves)
            {
                int f = ct & 127, half = ct >> 7;
                int k0 = half*64;
                float accc = 0.f, accg = 0.f;
#pragma unroll 16
                for (int kk = 0; kk < 64; kk++) {
                    int k = k0 + kk;
                    accc += sLG[k]*sW4l[k*128 + f];
                    accg += sh128[k]*sW4h[(k >> 1)*256 + 2*f + (k & 1)];
                }
                sCp[ct] = accc;
                sGp[ct] = accg;
            }
            BAR_CHAIN();
            float cf = 0.f, hn128 = 0.f;
            if (ct < 128) {
                cf = sCp[ct] + sCp[128 + ct] + ureg;
                sC[ct] = cf;
                float g128 = sGp[ct] + sGp[128 + ct] + cf;
                hn128 = sQE[128]*sLG[ct] + sigm(g128)*sh128[ct];
                sh128[ct] = hn128;
            }
            BAR3_ARRIVE();                     // publish sLG/sC/sQN
            BAR4_SYNC();                       // wait sPart

            float ownp = 0.f;
            if (ct < 128) {
                int half = ct >> 6, fo = ct & 63;
#pragma unroll
                for (int i = 0; i < 8; i++)
                    ownp += sPart[(half*8 + i)*64 + fo];
                st_async_f32(rPHT + ct*4, ownp, rmbT);
            }
            MBAR_WAIT(mbT, t & 1);
            if (ct < 128) {
                float v = __fdividef(ownp + pHT[ct] + sQN[128]*hn128,
                                     g_QS[b*NS + t + 1]);
                sHT[ct] = v;
                if (rank == 0) g_HT[(b*NS + t)*128 + ct] = v;
            }
            BAR_CHAIN();                       // sHT visible for next G-GEMV
        }
    }
}

// ============================ epilogue ======================================
__global__ void __launch_bounds__(128) lpkt_epi(
    const int* __restrict__ e_data, const float* __restrict__ E_e,
    const float* __restrict__ b5, float* __restrict__ pred)
{
    int b = blockIdx.x, f = threadIdx.x;
    __shared__ float sx[256];
    __shared__ float sr[4];
    float b5f = b5[f];
    if (blockIdx.y == 0 && f == 0) pred[b*NS] = 0.f;
    for (int tt = 0; tt < 11; tt++) {
        int t = blockIdx.y*11 + tt;
        int en = e_data[b*NS + t + 1];
        __syncthreads();
        sx[f]       = E_e[en*128 + f];
        sx[128 + f] = g_HT[(b*NS + t)*128 + f];
        __syncthreads();
        float acc = b5f;
        const float4* wp = (const float4*)(g_W5T + f*256);
        const float4* xp = (const float4*)sx;
#pragma unroll 8
        for (int k4 = 0; k4 < 64; k4++) {
            float4 wv = wp[k4], xv = xp[k4];
            acc += wv.x*xv.x + wv.y*xv.y + wv.z*xv.z + wv.w*xv.w;
        }
        float v = sigm(acc);
        v += __shfl_xor_sync(0xffffffffu, v, 16);
        v += __shfl_xor_sync(0xffffffffu, v, 8);
        v += __shfl_xor_sync(0xffffffffu, v, 4);
        v += __shfl_xor_sync(0xffffffffu, v, 2);
        v += __shfl_xor_sync(0xffffffffu, v, 1);
        if ((f & 31) == 0) sr[f >> 5] = v;
        __syncthreads();
        if (f == 0) pred[b*NS + t + 1] = (sr[0] + sr[1] + sr[2] + sr[3]) * (1.f/128.f);
    }
}

// ============================ launch ========================================
extern "C" void kernel_launch(void* const* d_in, const int* in_sizes, int n_in,
                              void* d_out, int out_size)
{
    const int*   e_data   = (const int*)  d_in[0];
    const int*   a_data   = (const int*)  d_in[1];
    const int*   it_data  = (const int*)  d_in[2];
    const int*   at_data  = (const int*)  d_in[3];
    const float* q_matrix = (const float*)d_in[4];
    const float* h0       = (const float*)d_in[5];
    const float* E_e      = (const float*)d_in[6];
    const float* E_at     = (const float*)d_in[7];
    const float* E_it     = (const float*)d_in[8];
    const float* W1       = (const float*)d_in[9];
    const float* b1       = (const float*)d_in[10];
    const float* W2       = (const float*)d_in[11];
    const float* b2       = (const float*)d_in[12];
    const float* W3       = (const float*)d_in[13];
    const float* b3       = (const float*)d_in[14];
    const float* W4       = (const float*)d_in[15];
    const float* b4       = (const float*)d_in[16];
    const float* W5       = (const float*)d_in[17];
    const float* b5       = (const float*)d_in[18];
    float* pred = (float*)d_out;

    const int SMEM_MAIN = SMEM_FLOATS * 4;   // 179,760 B
    cudaFuncSetAttribute(lpkt_main, cudaFuncAttributeMaxDynamicSharedMemorySize, SMEM_MAIN);

    prep_base<<<64, 512>>>(W1, W5, e_data, q_matrix);                       // idx 0
    prep_ALUIT<<<dim3(64, 13), 128>>>(e_data, a_data, at_data, it_data,
                                      E_e, E_at, E_it, W1, b1, W4, b4);     // idx 1
    prep_G23<<<dim3(64, 10), 256>>>(it_data, E_it, W2, b2, W3, b3);         // idx 2
    lpkt_main<<<128, 768, SMEM_MAIN>>>(e_data, q_matrix, h0, W4, W2, W3);   // idx 3
    lpkt_epi<<<dim3(64, 9), 128>>>(e_data, E_e, b5, pred);                  // idx 4
}

// round 15
// speedup vs baseline: 1.1804x; 1.1804x over previous
#include <cuda_runtime.h>
#include <cuda_bf16.h>

typedef unsigned long long u64;
typedef unsigned int u32;

#define NB 64
#define NS 100
#define NQ 129
#define DD 128

// -------------------- device scratch ---------------------------------------
__device__ __align__(16) float g_AL [NB*NS*DD];
__device__ __align__(16) float g_G23[NB*NS*2*DD];
__device__ __align__(16) float g_UIT[NB*NS*DD];
__device__ __align__(16) float g_HT [NB*NS*DD];
__device__ __align__(16) float g_W5T [DD*2*DD];   // [f][k]
__device__ __align__(16) float g_w1s [DD];
__device__ __align__(16) float g_QS  [NB*NS];
__device__ __align__(16) u32   g_WB  [8*16*32*4]; // B frags: [kt][ntg][lane][whi0,whi1,wlo0,wlo1]

__device__ __forceinline__ float sigm(float x) {
    return __fdividef(1.f, 1.f + __expf(-x));
}
__device__ __forceinline__ u32 pack_bf16x2(float lo, float hi) {
    u32 r;
    asm("cvt.rn.bf16x2.f32 %0, %1, %2;" : "=r"(r) : "f"(hi), "f"(lo));
    return r;
}
__device__ __forceinline__ float bf_lo(u32 p) { return __uint_as_float(p << 16); }
__device__ __forceinline__ float bf_hi(u32 p) { return __uint_as_float(p & 0xffff0000u); }

#define MMA_BF16(d, a, b0v, b1v) \
    asm volatile("mma.sync.aligned.m16n8k16.row.col.f32.bf16.bf16.f32 " \
        "{%0,%1,%2,%3}, {%4,%5,%6,%7}, {%8,%9}, {%0,%1,%2,%3};" \
        : "+f"((d)[0]), "+f"((d)[1]), "+f"((d)[2]), "+f"((d)[3]) \
        : "r"((a).x), "r"((a).y), "r"((a).z), "r"((a).w), "r"(b0v), "r"(b1v))

__device__ __forceinline__ u32 smem_u32(const void* p) {
    u32 a;
    asm("{ .reg .u64 t; cvta.to.shared.u64 t, %1; cvt.u32.u64 %0, t; }" : "=r"(a) : "l"(p));
    return a;
}
__device__ __forceinline__ u32 mapa_u32(u32 laddr, u32 r) {
    u32 a;
    asm("mapa.shared::cluster.u32 %0, %1, %2;" : "=r"(a) : "r"(laddr), "r"(r));
    return a;
}
__device__ __forceinline__ void st_cluster_f32(u32 raddr, float v) {
    asm volatile("st.shared::cluster.f32 [%0], %1;" :: "r"(raddr), "f"(v) : "memory");
}
__device__ __forceinline__ void st_async_f32(u32 raddr, float v, u32 rmbar) {
    asm volatile("st.async.shared::cluster.mbarrier::complete_tx::bytes.f32 [%0], %1, [%2];"
                 :: "r"(raddr), "f"(v), "r"(rmbar) : "memory");
}
#define CLUSTER_SYNC() do { \
    asm volatile("barrier.cluster.arrive.aligned;" ::: "memory"); \
    asm volatile("barrier.cluster.wait.aligned;"   ::: "memory"); \
} while (0)
#define MBARRIER_INIT(mb, c) \
    asm volatile("mbarrier.init.shared.b64 [%0], %1;" :: "r"((u32)(mb)), "r"((u32)(c)) : "memory")
#define MBAR_EXPECT_TX(mb, bytes) \
    asm volatile("mbarrier.arrive.expect_tx.shared.b64 _, [%0], %1;" \
                 :: "r"((u32)(mb)), "r"((u32)(bytes)) : "memory")
#define MBAR_WAIT(mb, par) do { \
    u32 _m = (u32)(mb), _p = (u32)(par), _d; \
    asm volatile("{ .reg .pred p; mbarrier.try_wait.parity.acquire.cta.shared::cta.b64 p, [%1], %2; selp.b32 %0, 1, 0, p; }" \
                 : "=r"(_d) : "r"(_m), "r"(_p) : "memory"); \
    if (!_d) { \
        asm volatile("{ .reg .pred P1; WL_%=: mbarrier.try_wait.parity.acquire.cta.shared::cta.b64 P1, [%0], %1, 0x989680; @P1 bra.uni WD_%=; bra.uni WL_%=; WD_%=: }" \
                     :: "r"(_m), "r"(_p) : "memory"); \
    } \
} while (0)
#define BAR_CHAIN()   asm volatile("bar.sync 1, 256;" ::: "memory")
#define BAR3_SYNC()   asm volatile("bar.sync 3, 512;" ::: "memory")
#define BAR3_ARRIVE() asm volatile("bar.arrive 3, 512;" ::: "memory")
#define BAR4_SYNC()   asm volatile("bar.sync 4, 512;" ::: "memory")
#define BAR4_ARRIVE() asm volatile("bar.arrive 4, 512;" ::: "memory")
#define BAR_GEMM()    asm volatile("bar.sync 5, 256;" ::: "memory")

// ============================ prep kernels ==================================
__global__ void prep_base(const float* __restrict__ W1, const float* __restrict__ W5,
                          const float* __restrict__ W4,
                          const int* __restrict__ e_data, const float* __restrict__ q_matrix)
{
    int gidx = blockIdx.x*blockDim.x + threadIdx.x;
    for (int idx = gidx; idx < 32896; idx += gridDim.x*blockDim.x) {
        if (idx < 32768) {
            int f = idx >> 8, k = idx & 255;
            g_W5T[idx] = W5[k*128 + f];
        } else {
            int f = idx - 32768;
            float s = 0.f;
            for (int k = 0; k < 128; k++) s += W1[(256+k)*128 + f];
            g_w1s[f] = s;
        }
    }
    // B fragments of W4h (hi/lo bf16 splits), m16n8k16 col-major B layout
    for (int e = gidx; e < 8*16*32; e += gridDim.x*blockDim.x) {
        int kt = e >> 9, rem = e & 511;
        int ntg = rem >> 5, lane = rem & 31;
        int gid = lane >> 2, tig = lane & 3;
        int k0 = kt*16 + 2*tig;
        int n  = ntg*8 + gid;
        float w00 = W4[(k0    )*128 + n], w01 = W4[(k0 + 1)*128 + n];
        float w10 = W4[(k0 + 8)*128 + n], w11 = W4[(k0 + 9)*128 + n];
        u32 whi0 = pack_bf16x2(w00, w01);
        u32 whi1 = pack_bf16x2(w10, w11);
        u32 wlo0 = pack_bf16x2(w00 - bf_lo(whi0), w01 - bf_hi(whi0));
        u32 wlo1 = pack_bf16x2(w10 - bf_lo(whi1), w11 - bf_hi(whi1));
        g_WB[e*4 + 0] = whi0; g_WB[e*4 + 1] = whi1;
        g_WB[e*4 + 2] = wlo0; g_WB[e*4 + 3] = wlo1;
    }
    // QS
    int lane = threadIdx.x & 31;
    int gw = gidx >> 5;
    int nw = (gridDim.x*blockDim.x) >> 5;
    for (int item = gw; item < NB*NS; item += nw) {
        const float* q = q_matrix + (long)e_data[item]*NQ;
        float s = 0.f;
        for (int i = lane; i < NQ; i += 32) s += q[i];
        s += __shfl_xor_sync(0xffffffffu, s, 16);
        s += __shfl_xor_sync(0xffffffffu, s, 8);
        s += __shfl_xor_sync(0xffffffffu, s, 4);
        s += __shfl_xor_sync(0xffffffffu, s, 2);
        s += __shfl_xor_sync(0xffffffffu, s, 1);
        if (lane == 0) g_QS[item] = s;
    }
}

__global__ void __launch_bounds__(128) prep_ALUIT(
    const int* __restrict__ e_data, const int* __restrict__ a_data,
    const int* __restrict__ at_data, const int* __restrict__ it_data,
    const float* __restrict__ E_e, const float* __restrict__ E_at,
    const float* __restrict__ E_it,
    const float* __restrict__ W1, const float* __restrict__ b1,
    const float* __restrict__ W4, const float* __restrict__ b4)
{
    int b = blockIdx.x, s0 = blockIdx.y*8, f = threadIdx.x;
    __shared__ float se[8][128], sa[8][128], si[8][128], av[8];
    int cnt = min(8, NS - s0);
    for (int t = 0; t < 8; t++) {
        if (t < cnt) {
            int s = s0 + t;
            se[t][f] = E_e [e_data [b*NS + s]*128 + f];
            sa[t][f] = E_at[at_data[b*NS + s]*128 + f];
            si[t][f] = E_it[it_data[b*NS + s]*128 + f];
            if (f == 0) av[t] = (float)a_data[b*NS + s];
        } else { se[t][f] = 0.f; sa[t][f] = 0.f; si[t][f] = 0.f; if (f == 0) av[t] = 0.f; }
    }
    __syncthreads();
    float w1sf = g_w1s[f], b1f = b1[f], b4f = b4[f];
    float acc[8], acu[8];
#pragma unroll
    for (int t = 0; t < 8; t++) { acc[t] = b1f + av[t]*w1sf; acu[t] = b4f; }
    for (int k = 0; k < 128; k++) {
        float w = W1[k*128 + f];
#pragma unroll
        for (int t = 0; t < 8; t++) acc[t] += se[t][k]*w;
    }
    for (int k = 0; k < 128; k++) {
        float w = W1[(128+k)*128 + f];
#pragma unroll
        for (int t = 0; t < 8; t++) acc[t] += sa[t][k]*w;
    }
    for (int k = 0; k < 128; k++) {
        float w = W4[(256+k)*128 + f];
#pragma unroll
        for (int t = 0; t < 8; t++) acu[t] += si[t][k]*w;
    }
    for (int t = 0; t < cnt; t++) {
        g_AL [(b*NS + s0 + t)*128 + f] = acc[t];
        g_UIT[(b*NS + s0 + t)*128 + f] = acu[t];
    }
}

__global__ void __launch_bounds__(256) prep_G23(
    const int* __restrict__ it_data, const float* __restrict__ E_it,
    const float* __restrict__ W2, const float* __restrict__ b2,
    const float* __restrict__ W3, const float* __restrict__ b3)
{
    int b = blockIdx.x, t0 = blockIdx.y*10;
    int T = min(10, 99 - t0);
    __shared__ float sf[10][384];
    for (int idx = threadIdx.x; idx < T*384; idx += 256) {
        int tt = idx / 384, kk = idx - tt*384;
        int t = t0 + tt;
        float v;
        if (kk < 128)       v = (t == 0) ? 0.f : g_AL[(b*NS + t - 1)*128 + kk];
        else if (kk < 256) { int it = it_data[b*NS + t]; v = E_it[it*128 + (kk-128)]; }
        else                v = g_AL[(b*NS + t)*128 + (kk-256)];
        sf[tt][kk] = v;
    }
    __syncthreads();
    int j = threadIdx.x;
    const float* Wc;
    float bias;
    if (j < 128) { Wc = W2 + j;        bias = b2[j];     }
    else         { Wc = W3 + (j-128);  bias = b3[j-128]; }
    float acc[10];
#pragma unroll
    for (int tt = 0; tt < 10; tt++) acc[tt] = bias;
    for (int k = 0; k < 384; k++) {
        float wv = Wc[k*128];
#pragma unroll
        for (int tt = 0; tt < 10; tt++) acc[tt] += sf[tt][k]*wv;
    }
    for (int tt = 0; tt < T; tt++) g_G23[(b*NS + t0 + tt)*256 + j] = acc[tt];
}

// ============================ main scan =====================================
// 2-CTA cluster per b, 512 threads. Warps 0..7: bf16 MMA GEMM (3-pass error
// split), each warp = (m-tile 16 rows, n-half 64 cols). Warps 8..15: chain.
// h kept f32 in sh (stride 130) + bf16 hi/lo A-fragments rewritten each step.
#define OFF_SH     0        // 64*130 = 8320
#define OFF_SH128  8320     // 128
#define OFF_W4L    8448     // 16384 [k][f]
#define OFF_LG     24832    // 128
#define OFF_C      24960    // 128
#define OFF_HT     25088    // 128
#define OFF_Q      25216    // 264
#define OFF_G2P    25480    // 256
#define OFF_G3P    25736    // 256
#define OFF_CP     25992    // 256
#define OFF_GP     26248    // 256
#define OFF_PHT    26504    // 128
#define OFF_MBAR   26632    // u64 (106528 B, 8-aligned)
#define OFF_AFH    26636    // 32 tiles * 32 lanes * 4 u32 = 4096 (16B-aligned)
#define OFF_AFL    30732    // 4096
#define OFF_WB     34828    // 16384 u32
#define SMEM_FLOATS 51212   // 204,848 B

__global__ void __launch_bounds__(512, 1) __cluster_dims__(2, 1, 1) lpkt_main(
    const int* __restrict__ e_data, const float* __restrict__ q_matrix,
    const float* __restrict__ h0, const float* __restrict__ W4,
    const float* __restrict__ W2, const float* __restrict__ W3)
{
    extern __shared__ float sm[];
    float* sh    = sm + OFF_SH;       // f32 h, row stride 130
    float* sh128 = sm + OFF_SH128;
    float* sW4l  = sm + OFF_W4L;
    float* sLG   = sm + OFF_LG;
    float* sC    = sm + OFF_C;
    float* sHT   = sm + OFF_HT;
    float* sQ    = sm + OFF_Q;
    float* sG2p  = sm + OFF_G2P;
    float* sG3p  = sm + OFF_G3P;
    float* sCp   = sm + OFF_CP;
    float* sGp   = sm + OFF_GP;
    float* pHT   = sm + OFF_PHT;
    u32*   sAFH  = (u32*)(sm + OFF_AFH);
    u32*   sAFL  = (u32*)(sm + OFF_AFL);
    u32*   sWB   = (u32*)(sm + OFF_WB);

    u32 rank;
    asm("mov.u32 %0, %%cluster_ctarank;" : "=r"(rank));
    const u32 peer = rank ^ 1u;
    const int b = blockIdx.x >> 1;
    const int tid = threadIdx.x;
    const int w = tid >> 5, lane = tid & 31;

    const u32 sb   = smem_u32(sm);
    const u32 mbT  = sb + OFF_MBAR*4;
    const u32 rmbT = mapa_u32(mbT, peer);
    const u32 rPHT = mapa_u32(sb + OFF_PHT*4, peer);

    // ---- init ----
    for (int idx = tid; idx < 16384; idx += 512) {
        sW4l[idx] = W4[16384 + idx];
        sWB[idx]  = g_WB[idx];
    }
    // h0 -> sh (f32) + A fragments (bf16 hi/lo)
    for (int idx = tid; idx < 4096; idx += 512) {
        int r = idx >> 6, p = idx & 63;
        int c = 2*p;
        float x0 = h0[(rank*64 + r)*128 + c];
        float x1 = h0[(rank*64 + r)*128 + c + 1];
        sh[r*130 + c]     = x0;
        sh[r*130 + c + 1] = x1;
        u32 hi = pack_bf16x2(x0, x1);
        u32 lo = pack_bf16x2(x0 - bf_lo(hi), x1 - bf_hi(hi));
        int T    = (c >> 4)*4 + (r >> 4);
        int lpos = (r & 7)*4 + ((c & 15) >> 1 & 3);
        int reg  = ((r >> 3) & 1) + (((c >> 3) & 1) << 1);
        sAFH[(T*32 + lpos)*4 + reg] = hi;
        sAFL[(T*32 + lpos)*4 + reg] = lo;
    }
    if (tid < 128) sh128[tid] = h0[16384 + tid];
    if (tid < NQ) sQ[tid] = q_matrix[(long)e_data[b*NS]*NQ + tid];
    if (tid == 0) MBARRIER_INIT(mbT, 1);
    __syncthreads();
    CLUSTER_SYNC();

    // ---- ht0 ----
    if (tid < 256) {
        int f = tid & 127, half = tid >> 7;
        float acc = 0.f;
        for (int rr = 0; rr < 32; rr++) {
            int rl = half*32 + rr;
            acc += sQ[rank*64 + rl]*sh[rl*130 + f];
        }
        sCp[tid] = acc;
    }
    __syncthreads();
    float own0 = 0.f;
    if (tid < 128) {
        own0 = sCp[tid] + sCp[128 + tid];
        st_cluster_f32(rPHT + tid*4, own0);
    }
    CLUSTER_SYNC();
    if (tid < 128)
        sHT[tid] = __fdividef(own0 + pHT[tid] + sQ[128]*sh128[tid], g_QS[b*NS]);
    __syncthreads();

    const int mt = w & 3;            // m-tile (16 rows)
    const int nh = w >> 2;           // n-half among GEMM warps (w<8)
    const int gid = lane >> 2, tig = lane & 3;

    for (int t = 0; t < 99; t++) {
        const float* sQE = sQ + (t & 1)*132;
        float*       sQN = sQ + ((t + 1) & 1)*132;

        if (w < 8) {
            // ============== MMA GEMM: 16 rows x 64 cols per warp ==============
            float acc[8][4];
#pragma unroll
            for (int nt = 0; nt < 8; nt++) {
                acc[nt][0] = 0.f; acc[nt][1] = 0.f; acc[nt][2] = 0.f; acc[nt][3] = 0.f;
            }
            const uint4* AH = (const uint4*)sAFH;
            const uint4* AL = (const uint4*)sAFL;
            const uint4* WBp = (const uint4*)sWB;
#pragma unroll 2
            for (int kt = 0; kt < 8; kt++) {
                uint4 ah = AH[(kt*4 + mt)*32 + lane];
                uint4 al = AL[(kt*4 + mt)*32 + lane];
#pragma unroll
                for (int nt = 0; nt < 8; nt++) {
                    uint4 wb = WBp[(kt*16 + nh*8 + nt)*32 + lane];
                    MMA_BF16(acc[nt], ah, wb.x, wb.y);
                    MMA_BF16(acc[nt], al, wb.x, wb.y);
                    MMA_BF16(acc[nt], ah, wb.z, wb.w);
                }
            }
            BAR3_SYNC();                       // sLG/sC/sQN ready

            // ---- epilogue: gate + h update + fragment rewrite ----
            int row0l = mt*16 + gid;
            float qe0 = sQE[rank*64 + row0l];
            float qe1 = sQE[rank*64 + row0l + 8];
#pragma unroll
            for (int nt = 0; nt < 8; nt++) {
                int c = nh*64 + nt*8 + 2*tig;
                float2 lg = *(const float2*)(sLG + c);
                float2 cf = *(const float2*)(sC + c);
                int T   = (c >> 4)*4 + mt;
                int rg2 = (nt & 1) << 1;
#pragma unroll
                for (int half = 0; half < 2; half++) {
                    int row = row0l + half*8;
                    float qe = half ? qe1 : qe0;
                    float g0 = acc[nt][2*half]     + cf.x;
                    float g1 = acc[nt][2*half + 1] + cf.y;
                    float2 hold = *(const float2*)(sh + row*130 + c);
                    float2 hn;
                    hn.x = qe*lg.x + sigm(g0)*hold.x;
                    hn.y = qe*lg.y + sigm(g1)*hold.y;
                    *(float2*)(sh + row*130 + c) = hn;
                    u32 hi = pack_bf16x2(hn.x, hn.y);
                    u32 lo = pack_bf16x2(hn.x - bf_lo(hi), hn.y - bf_hi(hi));
                    int reg = half + rg2;
                    sAFH[(T*32 + lane)*4 + reg] = hi;
                    sAFL[(T*32 + lane)*4 + reg] = lo;
                }
            }
            BAR4_ARRIVE();                     // sh published for chain
            BAR_GEMM();                        // AF frags complete among GEMM warps
        } else {
            // ================= chain warps =================
            const int ct = tid - 256;
            if (ct == 0) MBAR_EXPECT_TX(mbT, 512);
            float ureg = 0.f;
            if (ct < 128) ureg = g_UIT[(b*NS + t)*128 + ct];
            if (ct < NQ) sQN[ct] = q_matrix[(long)e_data[b*NS + t + 1]*NQ + ct];

            // G partials: k-split halves, W2 & W3 from L2
            {
                int j = ct & 127, kk0 = (ct >> 7)*64;
                const float* W2c = W2 + (384 + kk0)*128 + j;
                const float* W3c = W3 + (384 + kk0)*128 + j;
                const float* hpt = sHT + kk0;
                float a2[4] = {0.f, 0.f, 0.f, 0.f};
                float a3[4] = {0.f, 0.f, 0.f, 0.f};
#pragma unroll 8
                for (int kk = 0; kk < 64; kk++) {
                    float hv = hpt[kk];
                    a2[kk & 3] += hv*W2c[kk*128];
                    a3[kk & 3] += hv*W3c[kk*128];
                }
                sG2p[ct] = (a2[0] + a2[1]) + (a2[2] + a2[3]);
                sG3p[ct] = (a3[0] + a3[1]) + (a3[2] + a3[3]);
            }
            BAR_CHAIN();
            if (ct < 128) {
                const float* gb = g_G23 + (b*NS + t)*256;
                float g2 = sG2p[ct] + sG2p[128 + ct] + gb[ct];
                float g3 = sG3p[ct] + sG3p[128 + ct] + gb[128 + ct];
                sLG[ct] = sigm(g3) * sigm(2.f*g2);
            }
            BAR_CHAIN();

            // c = LG @ W4l (smem) ; g128 = h128 @ W4h (L2)
            {
                int f = ct & 127, half = ct >> 7;
                int k0 = half*64;
                const float* W4g = W4 + k0*128 + f;
                float accc = 0.f, accg = 0.f;
#pragma unroll 16
                for (int kk = 0; kk < 64; kk++) {
                    int k = k0 + kk;
                    accc += sLG[k]*sW4l[k*128 + f];
                    accg += sh128[k]*W4g[kk*128];
                }
                sCp[ct] = accc;
                sGp[ct] = accg;
            }
            BAR_CHAIN();
            float cf = 0.f, hn128 = 0.f;
            if (ct < 128) {
                cf = sCp[ct] + sCp[128 + ct] + ureg;
                sC[ct] = cf;
                float g128 = sGp[ct] + sGp[128 + ct] + cf;
                hn128 = sQE[128]*sLG[ct] + sigm(g128)*sh128[ct];
                sh128[ct] = hn128;
            }
            BAR3_ARRIVE();                     // publish sLG/sC/sQN
            BAR4_SYNC();                       // wait sh updated

            // h_tilde: GEMV over sh, DSMEM exchange
            {
                int f = ct & 127, half = ct >> 7;
                float htp = 0.f;
#pragma unroll 8
                for (int rr = 0; rr < 32; rr++) {
                    int rl = half*32 + rr;
                    htp += sQN[rank*64 + rl]*sh[rl*130 + f];
                }
                sCp[ct] = htp;
            }
            BAR_CHAIN();
            float ownp = 0.f;
            if (ct < 128) {
                ownp = sCp[ct] + sCp[128 + ct];
                st_async_f32(rPHT + ct*4, ownp, rmbT);
            }
            MBAR_WAIT(mbT, t & 1);
            if (ct < 128) {
                float v = __fdividef(ownp + pHT[ct] + sQN[128]*hn128,
                                     g_QS[b*NS + t + 1]);
                sHT[ct] = v;
                if (rank == 0) g_HT[(b*NS + t)*128 + ct] = v;
            }
            BAR_CHAIN();                       // sHT visible for next head
        }
    }
}

// ============================ epilogue ======================================
__global__ void __launch_bounds__(128) lpkt_epi(
    const int* __restrict__ e_data, const float* __restrict__ E_e,
    const float* __restrict__ b5, float* __restrict__ pred)
{
    int b = blockIdx.x, f = threadIdx.x;
    __shared__ float sx[256];
    __shared__ float sr[4];
    float b5f = b5[f];
    if (blockIdx.y == 0 && f == 0) pred[b*NS] = 0.f;
    for (int tt = 0; tt < 11; tt++) {
        int t = blockIdx.y*11 + tt;
        int en = e_data[b*NS + t + 1];
        __syncthreads();
        sx[f]       = E_e[en*128 + f];
        sx[128 + f] = g_HT[(b*NS + t)*128 + f];
        __syncthreads();
        float acc = b5f;
        const float4* wp = (const float4*)(g_W5T + f*256);
        const float4* xp = (const float4*)sx;
#pragma unroll 8
        for (int k4 = 0; k4 < 64; k4++) {
            float4 wv = wp[k4], xv = xp[k4];
            acc += wv.x*xv.x + wv.y*xv.y + wv.z*xv.z + wv.w*xv.w;
        }
        float v = sigm(acc);
        v += __shfl_xor_sync(0xffffffffu, v, 16);
        v += __shfl_xor_sync(0xffffffffu, v, 8);
        v += __shfl_xor_sync(0xffffffffu, v, 4);
        v += __shfl_xor_sync(0xffffffffu, v, 2);
        v += __shfl_xor_sync(0xffffffffu, v, 1);
        if ((f & 31) == 0) sr[f >> 5] = v;
        __syncthreads();
        if (f == 0) pred[b*NS + t + 1] = (sr[0] + sr[1] + sr[2] + sr[3]) * (1.f/128.f);
    }
}

// ============================ launch ========================================
extern "C" void kernel_launch(void* const* d_in, const int* in_sizes, int n_in,
                              void* d_out, int out_size)
{
    const int*   e_data   = (const int*)  d_in[0];
    const int*   a_data   = (const int*)  d_in[1];
    const int*   it_data  = (const int*)  d_in[2];
    const int*   at_data  = (const int*)  d_in[3];
    const float* q_matrix = (const float*)d_in[4];
    const float* h0       = (const float*)d_in[5];
    const float* E_e      = (const float*)d_in[6];
    const float* E_at     = (const float*)d_in[7];
    const float* E_it     = (const float*)d_in[8];
    const float* W1       = (const float*)d_in[9];
    const float* b1       = (const float*)d_in[10];
    const float* W2       = (const float*)d_in[11];
    const float* b2       = (const float*)d_in[12];
    const float* W3       = (const float*)d_in[13];
    const float* b3       = (const float*)d_in[14];
    const float* W4       = (const float*)d_in[15];
    const float* b4       = (const float*)d_in[16];
    const float* W5       = (const float*)d_in[17];
    const float* b5       = (const float*)d_in[18];
    float* pred = (float*)d_out;

    const int SMEM_MAIN = SMEM_FLOATS * 4;   // 204,848 B
    cudaFuncSetAttribute(lpkt_main, cudaFuncAttributeMaxDynamicSharedMemorySize, SMEM_MAIN);

    prep_base<<<64, 512>>>(W1, W5, W4, e_data, q_matrix);                   // idx 0
    prep_ALUIT<<<dim3(64, 13), 128>>>(e_data, a_data, at_data, it_data,
                                      E_e, E_at, E_it, W1, b1, W4, b4);     // idx 1
    prep_G23<<<dim3(64, 10), 256>>>(it_data, E_it, W2, b2, W3, b3);         // idx 2
    lpkt_main<<<128, 512, SMEM_MAIN>>>(e_data, q_matrix, h0, W4, W2, W3);   // idx 3
    lpkt_epi<<<dim3(64, 9), 128>>>(e_data, E_e, b5, pred);                  // idx 4
}